// round 13
// baseline (speedup 1.0000x reference)
#include <cuda_runtime.h>
#include <cuda_bf16.h>
#include <cstdint>

// ---------------- problem constants ----------------
#define BATCH 4
#define CDIM  256
#define DDIM  32
#define NPIX  4096
#define LN_EPS 1e-5f
#define SCALE_LOG2E 0.2550348639f   // (1/sqrt(32)) * log2(e)

#define MQ 128                      // queries per CTA
#define TK 128                      // keys per tile
#define NTILES (NPIX / TK)          // 32

// ---------------- scratch (bf16, MMA-friendly layouts) ----------------
__device__ __nv_bfloat16 g_q[(size_t)BATCH * NPIX * DDIM];   // [b][n][d], pre-scaled
__device__ __nv_bfloat16 g_k[(size_t)BATCH * DDIM * NPIX];   // [b][d][n]
__device__ __nv_bfloat16 g_v[(size_t)BATCH * NPIX * CDIM];   // [b][n][c]

// ---------------- attn smem layout (bytes, dynamic) ----------------
// QS:  128 x 80B                       [0,      10240)
// KS0: 32 x 272B / VS0: 128 x 528B     [10240,  86528)
// KS1 / VS1 (double buffer)            [86528, 162816)
// OutS overlay (128 x 516B)            [10240,  76288)
#define QS_OFF    0
#define KS_OFF    10240
#define VS_OFF    18944
#define BUFSTRIDE 76288
#define OUTS_OFF  10240
#define WS_OFF    162816
#define WQ_OFF    166912
#define MST_OFF   171008
#define LSTD_OFF  171520
#define SMEM_DYN  172032

// ---------------- PTX helpers (sm_100 base-target safe) ----------------
__device__ __forceinline__ uint32_t smem_u32(const void* p) {
    uint32_t a;
    asm("{ .reg .u64 t; cvta.to.shared.u64 t, %1; cvt.u32.u64 %0, t; }" : "=r"(a) : "l"(p));
    return a;
}
__device__ __forceinline__ float ex2f(float v) {
    float y; asm("ex2.approx.ftz.f32 %0, %1;" : "=f"(y) : "f"(v)); return y;
}
__device__ __forceinline__ void ldsm4(uint32_t* r, uint32_t addr) {
    asm volatile("ldmatrix.sync.aligned.m8n8.x4.shared.b16 {%0,%1,%2,%3}, [%4];"
                 : "=r"(r[0]), "=r"(r[1]), "=r"(r[2]), "=r"(r[3]) : "r"(addr));
}
__device__ __forceinline__ void ldsm4t(uint32_t* r, uint32_t addr) {
    asm volatile("ldmatrix.sync.aligned.m8n8.x4.trans.shared.b16 {%0,%1,%2,%3}, [%4];"
                 : "=r"(r[0]), "=r"(r[1]), "=r"(r[2]), "=r"(r[3]) : "r"(addr));
}
__device__ __forceinline__ void mma16816(float* c, const uint32_t* a, const uint32_t* b) {
    asm volatile("mma.sync.aligned.m16n8k16.row.col.f32.bf16.bf16.f32 "
                 "{%0,%1,%2,%3}, {%4,%5,%6,%7}, {%8,%9}, {%0,%1,%2,%3};"
                 : "+f"(c[0]), "+f"(c[1]), "+f"(c[2]), "+f"(c[3])
                 : "r"(a[0]), "r"(a[1]), "r"(a[2]), "r"(a[3]), "r"(b[0]), "r"(b[1]));
}
#define CP_ASYNC16(dst, src) \
    asm volatile("cp.async.cg.shared.global [%0], [%1], 16;" :: "r"(dst), "l"(src))
#define CP_COMMIT() asm volatile("cp.async.commit_group;" ::: "memory")
#define CP_WAIT0()  asm volatile("cp.async.wait_group 0;" ::: "memory")
#define CP_WAIT1()  asm volatile("cp.async.wait_group 1;" ::: "memory")
#define STS32(addr, a) \
    asm volatile("st.shared.b32 [%0], %1;" :: "r"(addr), "r"(a) : "memory")
#define STS16(addr, h) \
    asm volatile("st.shared.b16 [%0], %1;" :: "r"(addr), "h"(h) : "memory")
#define LDS32(res, addr) \
    asm volatile("ld.shared.b32 %0, [%1];" : "=r"(res) : "r"(addr))
#define LDS16(res, addr) \
    asm volatile("ld.shared.b16 %0, [%1];" : "=h"(res) : "r"(addr))
// pack {hi:lo} bf16x2
#define CVT_BF16X2(res, lo, hi) \
    asm("cvt.rn.bf16x2.f32 %0, %1, %2;" : "=r"(res) : "f"(hi), "f"(lo))

__device__ __forceinline__ uint16_t bf16_bits(float v) {
    uint32_t p; CVT_BF16X2(p, v, 0.0f); return (uint16_t)(p & 0xFFFFu);
}

// ---------------------------------------------------------------------------
// Kernel 1: QKV projection via bf16 mma.sync (round-10 version, unchanged).
// ---------------------------------------------------------------------------
#define WT_OFF 0        // 64 rows x 80B  = 5120
#define XT_OFF 5120     // 32 rows x 272B = 8704

__global__ __launch_bounds__(256) void qkv_kernel(
    const float* __restrict__ x,
    const float* __restrict__ wq, const float* __restrict__ bq,
    const float* __restrict__ wk, const float* __restrict__ bk,
    const float* __restrict__ wv, const float* __restrict__ bv)
{
    __shared__ __align__(16) char qsm[16896];
    const uint32_t sb = smem_u32(qsm);

    const int b  = blockIdx.z;
    const int n0 = blockIdx.x * 128;
    const int r0 = blockIdx.y * 64;
    const int tid  = threadIdx.x;
    const int lane = tid & 31;
    const int warp = tid >> 5;
    const int rgrp  = (warp & 3) * 16;
    const int nhalf = (warp >> 2) * 64;
    const int qg = lane >> 2, qt = lane & 3;
    const float* xb = x + (size_t)b * CDIM * NPIX;

    float acc[8][4];
#pragma unroll
    for (int i = 0; i < 8; i++)
#pragma unroll
        for (int j = 0; j < 4; j++) acc[i][j] = 0.0f;

    for (int kk = 0; kk < CDIM; kk += 32) {
#pragma unroll
        for (int l = 0; l < 4; l++) {
            int idx = tid + l * 256;
            int r = idx >> 4, cp = (idx & 15) * 2;
            int rg = r0 + r, c = kk + cp;
            const float* ws;
            if (rg < DDIM)            ws = wq + rg * CDIM + c;
            else if (rg < 2 * DDIM)   ws = wk + (rg - DDIM) * CDIM + c;
            else                      ws = wv + (rg - 2 * DDIM) * CDIM + c;
            float2 w2 = *reinterpret_cast<const float2*>(ws);
            uint32_t pw; CVT_BF16X2(pw, w2.x, w2.y);
            STS32(sb + WT_OFF + r * 80 + cp * 2, pw);
        }
#pragma unroll
        for (int l = 0; l < 8; l++) {
            int idx = tid + l * 256;
            int k = idx >> 6, np = (idx & 63) * 2;
            float2 x2 = *reinterpret_cast<const float2*>(xb + (size_t)(kk + k) * NPIX + n0 + np);
            uint32_t px; CVT_BF16X2(px, x2.x, x2.y);
            STS32(sb + XT_OFF + k * 272 + np * 2, px);
        }
        __syncthreads();

        uint32_t wa[2][4];
        {
            int r = rgrp + (lane & 7) + ((lane >> 3) & 1) * 8;
            int cb = (lane >> 4) * 16;
            ldsm4(wa[0], sb + WT_OFF + r * 80 + cb);
            ldsm4(wa[1], sb + WT_OFF + r * 80 + 32 + cb);
        }
        const uint32_t xaddr = sb + XT_OFF + lane * 272 + nhalf * 2;
#pragma unroll
        for (int nb = 0; nb < 8; nb++) {
            uint32_t bx[4];
            ldsm4t(bx, xaddr + nb * 16);
            mma16816(acc[nb], wa[0], bx);
            mma16816(acc[nb], wa[1], bx + 2);
        }
        __syncthreads();
    }

    // ---- bias + stage into T[n][r] (bf16, 132B row stride) ----
#pragma unroll
    for (int half = 0; half < 2; half++) {
        int rl = rgrp + qg + half * 8;
        int rg = r0 + rl;
        float bias;
        if (rg < DDIM)          bias = bq[rg];
        else if (rg < 2 * DDIM) bias = bk[rg - DDIM];
        else                    bias = bv[rg - 2 * DDIM];
        float mult = (rg < DDIM) ? SCALE_LOG2E : 1.0f;
#pragma unroll
        for (int nb = 0; nb < 8; nb++) {
            int nl = nhalf + nb * 8 + qt * 2;
            float v0 = (acc[nb][half * 2 + 0] + bias) * mult;
            float v1 = (acc[nb][half * 2 + 1] + bias) * mult;
            STS16(sb + nl * 132 + rl * 2, bf16_bits(v0));
            STS16(sb + (nl + 1) * 132 + rl * 2, bf16_bits(v1));
        }
    }
    __syncthreads();

    if (r0 == 0) {
        // q rows 0..31 -> g_q[b][n][d]
#pragma unroll
        for (int l = 0; l < 8; l++) {
            int idx = tid + l * 256;
            int n = idx >> 4, rp = (idx & 15) * 2;
            uint32_t w; LDS32(w, sb + n * 132 + rp * 2);
            *reinterpret_cast<uint32_t*>(&g_q[((size_t)b * NPIX + n0 + n) * DDIM + rp]) = w;
        }
        // k rows 32..63 -> g_k[b][d][n]
#pragma unroll
        for (int l = 0; l < 8; l++) {
            int idx = tid + l * 256;
            int r = 32 + (idx >> 6), np = (idx & 63) * 2;
            uint16_t h0, h1;
            LDS16(h0, sb + np * 132 + r * 2);
            LDS16(h1, sb + (np + 1) * 132 + r * 2);
            uint32_t w = (uint32_t)h0 | ((uint32_t)h1 << 16);
            *reinterpret_cast<uint32_t*>(&g_k[((size_t)b * DDIM + (r - 32)) * NPIX + n0 + np]) = w;
        }
    } else {
        // v channels [r0-64, r0) -> g_v[b][n][c]
#pragma unroll
        for (int l = 0; l < 16; l++) {
            int idx = tid + l * 256;
            int n = idx >> 5, cp = (idx & 31) * 2;
            uint32_t w; LDS32(w, sb + n * 132 + cp * 2);
            *reinterpret_cast<uint32_t*>(&g_v[((size_t)b * NPIX + n0 + n) * CDIM + (r0 - 64) + cp]) = w;
        }
    }
}

// ---------------------------------------------------------------------------
// Kernel 2: mma.sync bf16 flash attention + gamma residual + LayerNorm.
// 256 threads / 8 warps: warp = (qpair 0..3 -> 32 queries, chalf 0..1 -> 128 ch).
// V fragments reused across two 16-row blocks (halves V smem traffic).
// GEMM1 duplicated across the chalf pair (P stays register-resident).
// ---------------------------------------------------------------------------

#define S_LOAD(hs) do {                                                     \
    ldsm4t(bka, kaddr + (uint32_t)(2*(hs)) * 16u);                          \
    ldsm4t(bkb, kaddr + (uint32_t)(2*(hs)+1) * 16u);                        \
} while (0)

// S for 16 keys x 32 rows: c8a = rows qg/qg+8, c8b = rows qg+16/qg+24
#define S_MMA_AB() do {                                                     \
    c8a[0]=c8a[1]=c8a[2]=c8a[3]=0.0f; c8a[4]=c8a[5]=c8a[6]=c8a[7]=0.0f;     \
    c8b[0]=c8b[1]=c8b[2]=c8b[3]=0.0f; c8b[4]=c8b[5]=c8b[6]=c8b[7]=0.0f;     \
    mma16816(c8a,     qa0[0], bka);                                         \
    mma16816(c8b,     qa1[0], bka);                                         \
    mma16816(c8a + 4, qa0[0], bkb);                                         \
    mma16816(c8b + 4, qa1[0], bkb);                                         \
    mma16816(c8a,     qa0[1], bka + 2);                                     \
    mma16816(c8b,     qa1[1], bka + 2);                                     \
    mma16816(c8a + 4, qa0[1], bkb + 2);                                     \
    mma16816(c8b + 4, qa1[1], bkb + 2);                                     \
} while (0)

#define SOFTMAX_ONE(c8, P, la, lb) do {                                     \
    float e0_=ex2f((c8)[0]), e1_=ex2f((c8)[1]);                             \
    float e2_=ex2f((c8)[2]), e3_=ex2f((c8)[3]);                             \
    float f0_=ex2f((c8)[4]), f1_=ex2f((c8)[5]);                             \
    float f2_=ex2f((c8)[6]), f3_=ex2f((c8)[7]);                             \
    (la) += e0_ + e1_ + f0_ + f1_;                                          \
    (lb) += e2_ + e3_ + f2_ + f3_;                                          \
    CVT_BF16X2((P)[0], e0_, e1_);                                           \
    CVT_BF16X2((P)[1], e2_, e3_);                                           \
    CVT_BF16X2((P)[2], f0_, f1_);                                           \
    CVT_BF16X2((P)[3], f2_, f3_);                                           \
} while (0)

// GEMM2 over warp's 128 channels: each V ldsm feeds 4 mma (2 rowsets x 2 nb)
#define GEMM2_STEP(hs) do {                                                 \
    const uint32_t va_ = vbase + (uint32_t)(hs) * 8448u;                    \
    _Pragma("unroll")                                                       \
    for (int j_ = 0; j_ < 8; j_++) {                                        \
        uint32_t bv4_[4];                                                   \
        ldsm4t(bv4_, va_ + (uint32_t)(j_ * 32));                            \
        mma16816(oa[2*j_],     Pa, bv4_);                                   \
        mma16816(ob[2*j_],     Pb, bv4_);                                   \
        mma16816(oa[2*j_ + 1], Pa, bv4_ + 2);                               \
        mma16816(ob[2*j_ + 1], Pb, bv4_ + 2);                               \
    }                                                                       \
} while (0)

__global__ __launch_bounds__(256, 1) void attn_kernel(
    const float* __restrict__ x,
    const float* __restrict__ gamma,
    const float* __restrict__ ln_w,
    const float* __restrict__ ln_b,
    float* __restrict__ out)
{
    extern __shared__ char dsm[];
    const uint32_t sb = smem_u32(dsm);

    const int b  = blockIdx.y;
    const int n0 = blockIdx.x * MQ;
    const int tid  = threadIdx.x;
    const int lane = tid & 31;
    const int warp = tid >> 5;
    const int qpair = warp & 3;        // 32 queries
    const int chalf = warp >> 2;       // 128 channels
    const int wbase = qpair * 32;
    const int qg = lane >> 2, qt = lane & 3;

    const __nv_bfloat16* qb = g_q + (size_t)b * NPIX * DDIM;
    const __nv_bfloat16* kb = g_k + (size_t)b * DDIM * NPIX;
    const __nv_bfloat16* vb = g_v + (size_t)b * NPIX * CDIM;

    // ---- prologue: Q + tile0 into buffer 0 ----
#pragma unroll
    for (int i = 0; i < 2; i++) {
        int idx = tid + i * 256;
        int row = idx >> 2, ch = idx & 3;
        CP_ASYNC16(sb + QS_OFF + row * 80 + ch * 16,
                   (const char*)(qb + (size_t)(n0 + row) * DDIM) + ch * 16);
    }
#pragma unroll
    for (int i = 0; i < 2; i++) {
        int idx = tid + i * 256;
        int d = idx >> 4, ch = idx & 15;
        CP_ASYNC16(sb + KS_OFF + d * 272 + ch * 16,
                   (const char*)(kb + (size_t)d * NPIX) + ch * 16);
    }
#pragma unroll
    for (int i = 0; i < 16; i++) {
        int idx = tid + i * 256;
        int row = idx >> 5, c2 = idx & 31;
        CP_ASYNC16(sb + VS_OFF + row * 528 + c2 * 16,
                   (const char*)(vb + (size_t)row * CDIM) + c2 * 16);
    }
    CP_COMMIT();

    uint32_t qa0[2][4], qa1[2][4];
    float oa[16][4], ob[16][4];
#pragma unroll
    for (int nb = 0; nb < 16; nb++)
#pragma unroll
        for (int j = 0; j < 4; j++) { oa[nb][j] = 0.0f; ob[nb][j] = 0.0f; }
    float lsum0 = 0.0f, lsum1 = 0.0f, lsum2 = 0.0f, lsum3 = 0.0f;

    for (int kt = 0; kt < NTILES; kt++) {
        // issue next tile into the other buffer
        if (kt < NTILES - 1) {
            const int k0n = (kt + 1) * TK;
            const uint32_t bo = ((kt + 1) & 1) * BUFSTRIDE;
#pragma unroll
            for (int i = 0; i < 2; i++) {
                int idx = tid + i * 256;
                int d = idx >> 4, ch = idx & 15;
                CP_ASYNC16(sb + KS_OFF + bo + d * 272 + ch * 16,
                           (const char*)(kb + (size_t)d * NPIX + k0n) + ch * 16);
            }
#pragma unroll
            for (int i = 0; i < 16; i++) {
                int idx = tid + i * 256;
                int row = idx >> 5, c2 = idx & 31;
                CP_ASYNC16(sb + VS_OFF + bo + row * 528 + c2 * 16,
                           (const char*)(vb + (size_t)(k0n + row) * CDIM) + c2 * 16);
            }
            CP_COMMIT();
            CP_WAIT1();
        } else {
            CP_WAIT0();
        }
        __syncthreads();

        if (kt == 0) {
            int r  = wbase + (lane & 7) + ((lane >> 3) & 1) * 8;
            int cb = (lane >> 4) * 16;
            ldsm4(qa0[0], sb + QS_OFF + r * 80 + cb);
            ldsm4(qa0[1], sb + QS_OFF + r * 80 + 32 + cb);
            ldsm4(qa1[0], sb + QS_OFF + (r + 16) * 80 + cb);
            ldsm4(qa1[1], sb + QS_OFF + (r + 16) * 80 + 32 + cb);
        }

        const uint32_t bo = (kt & 1) * BUFSTRIDE;
        const uint32_t kaddr = sb + KS_OFF + bo + lane * 272;
        const uint32_t vbase = sb + VS_OFF + bo + (lane & 15) * 528 + (lane >> 4) * 16
                               + (uint32_t)chalf * 256u;

        // ---- pipelined: S_LOAD(hs+1) ... GEMM2(hs) ... S_MMA(hs+1) ----
        float c8a[8], c8b[8];
        uint32_t Pa[4], Pb[4], bka[4], bkb[4];
        S_LOAD(0);
        S_MMA_AB();
        SOFTMAX_ONE(c8a, Pa, lsum0, lsum1);
        SOFTMAX_ONE(c8b, Pb, lsum2, lsum3);
#pragma unroll
        for (int hs = 0; hs < 7; hs++) {
            S_LOAD(hs + 1);         // K-ldsm latency hides under GEMM2
            GEMM2_STEP(hs);         // consumes Pa/Pb; V fragments reused x4
            S_MMA_AB();             // operands long since arrived
            SOFTMAX_ONE(c8a, Pa, lsum0, lsum1);
            SOFTMAX_ONE(c8b, Pb, lsum2, lsum3);
        }
        GEMM2_STEP(7);
        __syncthreads();
    }

    // ---- row sums -> scale (warp-local: warp saw all 4096 keys) ----
#pragma unroll
    for (int off = 1; off <= 2; off <<= 1) {
        lsum0 += __shfl_xor_sync(0xffffffffu, lsum0, off);
        lsum1 += __shfl_xor_sync(0xffffffffu, lsum1, off);
        lsum2 += __shfl_xor_sync(0xffffffffu, lsum2, off);
        lsum3 += __shfl_xor_sync(0xffffffffu, lsum3, off);
    }
    const float gam = gamma[0];
    const float scl0 = gam / lsum0;
    const float scl1 = gam / lsum1;
    const float scl2 = gam / lsum2;
    const float scl3 = gam / lsum3;

    // ---- write scaled O to OutS (bf16, 516B row stride) ----
    {
        const uint32_t rbase = sb + OUTS_OFF + (uint32_t)(wbase + qg) * 516u;
#pragma unroll
        for (int nb = 0; nb < 16; nb++) {
            const uint32_t cbyte = (uint32_t)(chalf * 128 + nb * 8 + 2 * qt) * 2u;
            uint32_t p0, p1, p2, p3;
            CVT_BF16X2(p0, oa[nb][0] * scl0, oa[nb][1] * scl0);
            CVT_BF16X2(p1, oa[nb][2] * scl1, oa[nb][3] * scl1);
            CVT_BF16X2(p2, ob[nb][0] * scl2, ob[nb][1] * scl2);
            CVT_BF16X2(p3, ob[nb][2] * scl3, ob[nb][3] * scl3);
            STS32(rbase + cbyte, p0);
            STS32(rbase + 8u * 516u + cbyte, p1);
            STS32(rbase + 16u * 516u + cbyte, p2);
            STS32(rbase + 24u * 516u + cbyte, p3);
        }
    }
    __syncthreads();

    // ---- residual + LayerNorm: 256 threads = 256 channels, 2 x 64 pixels ----
    const int c = tid;
    const float lw = ln_w[c], lb = ln_b[c];
    float* wsum = reinterpret_cast<float*>(dsm + WS_OFF);
    float* wsq  = reinterpret_cast<float*>(dsm + WQ_OFF);
    float* mst  = reinterpret_cast<float*>(dsm + MST_OFF);
    float* lstd = reinterpret_cast<float*>(dsm + LSTD_OFF);
    const __nv_bfloat16* outs = reinterpret_cast<const __nv_bfloat16*>(dsm + OUTS_OFF);

    for (int hh = 0; hh < 2; hh++) {
        const int q0 = hh * 64;
        float Oc[64];
        const float* xrow = x + ((size_t)b * CDIM + c) * NPIX + n0 + q0;
#pragma unroll
        for (int j4 = 0; j4 < 16; j4++) {
            float4 xv = reinterpret_cast<const float4*>(xrow)[j4];
            float o0 = __bfloat162float(outs[(size_t)(q0 + 4 * j4 + 0) * 258 + c]);
            float o1 = __bfloat162float(outs[(size_t)(q0 + 4 * j4 + 1) * 258 + c]);
            float o2 = __bfloat162float(outs[(size_t)(q0 + 4 * j4 + 2) * 258 + c]);
            float o3 = __bfloat162float(outs[(size_t)(q0 + 4 * j4 + 3) * 258 + c]);
            Oc[4 * j4 + 0] = o0 + xv.x;
            Oc[4 * j4 + 1] = o1 + xv.y;
            Oc[4 * j4 + 2] = o2 + xv.z;
            Oc[4 * j4 + 3] = o3 + xv.w;
        }
#pragma unroll
        for (int q = 0; q < 64; q++) {
            float v = Oc[q];
            float s = v, s2 = v * v;
#pragma unroll
            for (int off = 16; off; off >>= 1) {
                s  += __shfl_xor_sync(0xffffffffu, s,  off);
                s2 += __shfl_xor_sync(0xffffffffu, s2, off);
            }
            if (lane == 0) { wsum[q * 8 + warp] = s; wsq[q * 8 + warp] = s2; }
        }
        __syncthreads();
        if (tid < 64) {
            float s = 0.0f, s2 = 0.0f;
#pragma unroll
            for (int w = 0; w < 8; w++) { s += wsum[tid * 8 + w]; s2 += wsq[tid * 8 + w]; }
            float mu  = s * (1.0f / CDIM);
            float var = s2 * (1.0f / CDIM) - mu * mu;
            mst[tid]  = mu;
            lstd[tid] = rsqrtf(var + LN_EPS);
        }
        __syncthreads();
        float* orow = out + ((size_t)b * CDIM + c) * NPIX + n0 + q0;
#pragma unroll
        for (int j4 = 0; j4 < 16; j4++) {
            float4 y;
            y.x = fmaf((Oc[4*j4 + 0] - mst[4*j4 + 0]) * lstd[4*j4 + 0], lw, lb);
            y.y = fmaf((Oc[4*j4 + 1] - mst[4*j4 + 1]) * lstd[4*j4 + 1], lw, lb);
            y.z = fmaf((Oc[4*j4 + 2] - mst[4*j4 + 2]) * lstd[4*j4 + 2], lw, lb);
            y.w = fmaf((Oc[4*j4 + 3] - mst[4*j4 + 3]) * lstd[4*j4 + 3], lw, lb);
            reinterpret_cast<float4*>(orow)[j4] = y;
        }
        __syncthreads();
    }
}

// ---------------------------------------------------------------------------
extern "C" void kernel_launch(void* const* d_in, const int* in_sizes, int n_in,
                              void* d_out, int out_size)
{
    const float* x     = (const float*)d_in[0];
    const float* wq    = (const float*)d_in[1];
    const float* bq    = (const float*)d_in[2];
    const float* wk    = (const float*)d_in[3];
    const float* bk    = (const float*)d_in[4];
    const float* wv    = (const float*)d_in[5];
    const float* bv    = (const float*)d_in[6];
    const float* gamma = (const float*)d_in[7];
    const float* ln_w  = (const float*)d_in[8];
    const float* ln_b  = (const float*)d_in[9];
    float* out = (float*)d_out;

    cudaFuncSetAttribute(attn_kernel, cudaFuncAttributeMaxDynamicSharedMemorySize, SMEM_DYN);

    qkv_kernel<<<dim3(NPIX / 128, 5, BATCH), 256>>>(x, wq, bq, wk, bk, wv, bv);
    attn_kernel<<<dim3(NPIX / MQ, BATCH), 256, SMEM_DYN>>>(x, gamma, ln_w, ln_b, out);
}

// round 14
// speedup vs baseline: 1.1022x; 1.1022x over previous
#include <cuda_runtime.h>
#include <cuda_bf16.h>
#include <cstdint>

// ---------------- problem constants ----------------
#define BATCH 4
#define CDIM  256
#define DDIM  32
#define NPIX  4096
#define LN_EPS 1e-5f
#define SCALE_LOG2E 0.2550348639f   // (1/sqrt(32)) * log2(e)

#define MQ 128                      // queries per CTA
#define TK 128                      // keys per tile
#define NTILES (NPIX / TK)          // 32

// ---------------- scratch (bf16, MMA-friendly layouts) ----------------
__device__ __nv_bfloat16 g_q[(size_t)BATCH * NPIX * DDIM];   // [b][n][d], pre-scaled
__device__ __nv_bfloat16 g_k[(size_t)BATCH * DDIM * NPIX];   // [b][d][n]
__device__ __nv_bfloat16 g_v[(size_t)BATCH * NPIX * CDIM];   // [b][n][c]

// ---------------- attn smem layout (bytes, dynamic) ----------------
// QS:  128 x 80B                       [0,      10240)
// KS0: 32 x 272B / VS0: 128 x 528B     [10240,  86528)
// KS1 / VS1 (double buffer)            [86528, 162816)
// OutS overlay (128 x 516B)            [10240,  76288)
#define QS_OFF    0
#define KS_OFF    10240
#define VS_OFF    18944
#define BUFSTRIDE 76288
#define OUTS_OFF  10240
#define WS_OFF    162816
#define WQ_OFF    166912
#define MST_OFF   171008
#define LSTD_OFF  171520
#define SMEM_DYN  172032

// ---------------- PTX helpers (sm_100 base-target safe) ----------------
__device__ __forceinline__ uint32_t smem_u32(const void* p) {
    uint32_t a;
    asm("{ .reg .u64 t; cvta.to.shared.u64 t, %1; cvt.u32.u64 %0, t; }" : "=r"(a) : "l"(p));
    return a;
}
__device__ __forceinline__ float ex2f(float v) {
    float y; asm("ex2.approx.ftz.f32 %0, %1;" : "=f"(y) : "f"(v)); return y;
}
__device__ __forceinline__ void ldsm4(uint32_t* r, uint32_t addr) {
    asm volatile("ldmatrix.sync.aligned.m8n8.x4.shared.b16 {%0,%1,%2,%3}, [%4];"
                 : "=r"(r[0]), "=r"(r[1]), "=r"(r[2]), "=r"(r[3]) : "r"(addr));
}
__device__ __forceinline__ void ldsm4t(uint32_t* r, uint32_t addr) {
    asm volatile("ldmatrix.sync.aligned.m8n8.x4.trans.shared.b16 {%0,%1,%2,%3}, [%4];"
                 : "=r"(r[0]), "=r"(r[1]), "=r"(r[2]), "=r"(r[3]) : "r"(addr));
}
__device__ __forceinline__ void mma16816(float* c, const uint32_t* a, const uint32_t* b) {
    asm volatile("mma.sync.aligned.m16n8k16.row.col.f32.bf16.bf16.f32 "
                 "{%0,%1,%2,%3}, {%4,%5,%6,%7}, {%8,%9}, {%0,%1,%2,%3};"
                 : "+f"(c[0]), "+f"(c[1]), "+f"(c[2]), "+f"(c[3])
                 : "r"(a[0]), "r"(a[1]), "r"(a[2]), "r"(a[3]), "r"(b[0]), "r"(b[1]));
}
#define CP_ASYNC16(dst, src) \
    asm volatile("cp.async.cg.shared.global [%0], [%1], 16;" :: "r"(dst), "l"(src))
#define CP_COMMIT() asm volatile("cp.async.commit_group;" ::: "memory")
#define CP_WAIT0()  asm volatile("cp.async.wait_group 0;" ::: "memory")
#define CP_WAIT1()  asm volatile("cp.async.wait_group 1;" ::: "memory")
#define STS32(addr, a) \
    asm volatile("st.shared.b32 [%0], %1;" :: "r"(addr), "r"(a) : "memory")
#define STS16(addr, h) \
    asm volatile("st.shared.b16 [%0], %1;" :: "r"(addr), "h"(h) : "memory")
#define LDS32(res, addr) \
    asm volatile("ld.shared.b32 %0, [%1];" : "=r"(res) : "r"(addr))
#define LDS16(res, addr) \
    asm volatile("ld.shared.b16 %0, [%1];" : "=h"(res) : "r"(addr))
// pack {hi:lo} bf16x2
#define CVT_BF16X2(res, lo, hi) \
    asm("cvt.rn.bf16x2.f32 %0, %1, %2;" : "=r"(res) : "f"(hi), "f"(lo))

__device__ __forceinline__ uint16_t bf16_bits(float v) {
    uint32_t p; CVT_BF16X2(p, v, 0.0f); return (uint16_t)(p & 0xFFFFu);
}

// ---------------------------------------------------------------------------
// Kernel 1: QKV projection via bf16 mma.sync.
// Round-14: n-tile widened to 256 (320 CTAs): W-tile loads and barriers per
// output halve; total HMMA unchanged.
// CTA: 64 r-rows x 256 n-cols, 256 threads / 8 warps (4 rgroups x 2 n-halves).
// ---------------------------------------------------------------------------
#define WT_OFF 0        // 64 rows x 80B  = 5120
#define XT_OFF 5120     // 32 rows x 528B = 16896  (end 22016)
// T overlay (output transpose): 256 n x 132B = 33792

__global__ __launch_bounds__(256) void qkv_kernel(
    const float* __restrict__ x,
    const float* __restrict__ wq, const float* __restrict__ bq,
    const float* __restrict__ wk, const float* __restrict__ bk,
    const float* __restrict__ wv, const float* __restrict__ bv)
{
    __shared__ __align__(16) char qsm[33792];
    const uint32_t sb = smem_u32(qsm);

    const int b  = blockIdx.z;
    const int n0 = blockIdx.x * 256;
    const int r0 = blockIdx.y * 64;
    const int tid  = threadIdx.x;
    const int lane = tid & 31;
    const int warp = tid >> 5;
    const int rgrp  = (warp & 3) * 16;
    const int nhalf = (warp >> 2) * 128;
    const int qg = lane >> 2, qt = lane & 3;
    const float* xb = x + (size_t)b * CDIM * NPIX;

    float acc[16][4];
#pragma unroll
    for (int i = 0; i < 16; i++)
#pragma unroll
        for (int j = 0; j < 4; j++) acc[i][j] = 0.0f;

    for (int kk = 0; kk < CDIM; kk += 32) {
        // W tile: 64 r x 32 c fp32 -> bf16 (pairs)
#pragma unroll
        for (int l = 0; l < 4; l++) {
            int idx = tid + l * 256;
            int r = idx >> 4, cp = (idx & 15) * 2;
            int rg = r0 + r, c = kk + cp;
            const float* ws;
            if (rg < DDIM)            ws = wq + rg * CDIM + c;
            else if (rg < 2 * DDIM)   ws = wk + (rg - DDIM) * CDIM + c;
            else                      ws = wv + (rg - 2 * DDIM) * CDIM + c;
            float2 w2 = *reinterpret_cast<const float2*>(ws);
            uint32_t pw; CVT_BF16X2(pw, w2.x, w2.y);
            STS32(sb + WT_OFF + r * 80 + cp * 2, pw);
        }
        // X tile: 32 k x 256 n fp32 -> bf16 (pairs, coalesced)
#pragma unroll
        for (int l = 0; l < 16; l++) {
            int idx = tid + l * 256;
            int k = idx >> 7, np = (idx & 127) * 2;
            float2 x2 = *reinterpret_cast<const float2*>(xb + (size_t)(kk + k) * NPIX + n0 + np);
            uint32_t px; CVT_BF16X2(px, x2.x, x2.y);
            STS32(sb + XT_OFF + k * 528 + np * 2, px);
        }
        __syncthreads();

        uint32_t wa[2][4];
        {
            int r = rgrp + (lane & 7) + ((lane >> 3) & 1) * 8;
            int cb = (lane >> 4) * 16;
            ldsm4(wa[0], sb + WT_OFF + r * 80 + cb);
            ldsm4(wa[1], sb + WT_OFF + r * 80 + 32 + cb);
        }
        const uint32_t xaddr = sb + XT_OFF + lane * 528 + nhalf * 2;
#pragma unroll
        for (int nb = 0; nb < 16; nb++) {
            uint32_t bx[4];
            ldsm4t(bx, xaddr + nb * 16);
            mma16816(acc[nb], wa[0], bx);
            mma16816(acc[nb], wa[1], bx + 2);
        }
        __syncthreads();
    }

    // ---- bias + stage into T[n][r] (bf16, 132B row stride) ----
#pragma unroll
    for (int half = 0; half < 2; half++) {
        int rl = rgrp + qg + half * 8;
        int rg = r0 + rl;
        float bias;
        if (rg < DDIM)          bias = bq[rg];
        else if (rg < 2 * DDIM) bias = bk[rg - DDIM];
        else                    bias = bv[rg - 2 * DDIM];
        float mult = (rg < DDIM) ? SCALE_LOG2E : 1.0f;
#pragma unroll
        for (int nb = 0; nb < 16; nb++) {
            int nl = nhalf + nb * 8 + qt * 2;
            float v0 = (acc[nb][half * 2 + 0] + bias) * mult;
            float v1 = (acc[nb][half * 2 + 1] + bias) * mult;
            STS16(sb + nl * 132 + rl * 2, bf16_bits(v0));
            STS16(sb + (nl + 1) * 132 + rl * 2, bf16_bits(v1));
        }
    }
    __syncthreads();

    if (r0 == 0) {
        // q rows 0..31 -> g_q[b][n][d]  (d contiguous)
#pragma unroll
        for (int l = 0; l < 16; l++) {
            int idx = tid + l * 256;
            int n = idx >> 4, rp = (idx & 15) * 2;
            uint32_t w; LDS32(w, sb + n * 132 + rp * 2);
            *reinterpret_cast<uint32_t*>(&g_q[((size_t)b * NPIX + n0 + n) * DDIM + rp]) = w;
        }
        // k rows 32..63 -> g_k[b][d][n]  (n contiguous)
#pragma unroll
        for (int l = 0; l < 16; l++) {
            int idx = tid + l * 256;
            int r = 32 + (idx >> 7), np = (idx & 127) * 2;
            uint16_t h0, h1;
            LDS16(h0, sb + np * 132 + r * 2);
            LDS16(h1, sb + (np + 1) * 132 + r * 2);
            uint32_t w = (uint32_t)h0 | ((uint32_t)h1 << 16);
            *reinterpret_cast<uint32_t*>(&g_k[((size_t)b * DDIM + (r - 32)) * NPIX + n0 + np]) = w;
        }
    } else {
        // v channels [r0-64, r0) -> g_v[b][n][c]  (c contiguous)
#pragma unroll
        for (int l = 0; l < 32; l++) {
            int idx = tid + l * 256;
            int n = idx >> 5, cp = (idx & 31) * 2;
            uint32_t w; LDS32(w, sb + n * 132 + cp * 2);
            *reinterpret_cast<uint32_t*>(&g_v[((size_t)b * NPIX + n0 + n) * CDIM + (r0 - 64) + cp]) = w;
        }
    }
}

// ---------------------------------------------------------------------------
// Kernel 2: mma.sync bf16 flash attention + gamma residual + LayerNorm.
// Round-10 champion, verbatim. 256 threads / 8 warps: warp = 16 queries x
// ALL 256 channels, 255-reg budget, double-buffered K/V, pipelined tile loop.
// ---------------------------------------------------------------------------

#define S_STEP(s, c8) do {                                                  \
    uint32_t bk4a_[4], bk4b_[4];                                            \
    (c8)[0]=(c8)[1]=(c8)[2]=(c8)[3]=0.0f;                                   \
    (c8)[4]=(c8)[5]=(c8)[6]=(c8)[7]=0.0f;                                   \
    ldsm4t(bk4a_, kaddr + (uint32_t)(2*(s)) * 16u);                         \
    ldsm4t(bk4b_, kaddr + (uint32_t)(2*(s)+1) * 16u);                       \
    mma16816((c8),     qa[0], bk4a_);                                       \
    mma16816((c8) + 4, qa[0], bk4b_);                                       \
    mma16816((c8),     qa[1], bk4a_ + 2);                                   \
    mma16816((c8) + 4, qa[1], bk4b_ + 2);                                   \
} while (0)

#define SOFTMAX_STEP(c8, P) do {                                            \
    float e0_=ex2f((c8)[0]), e1_=ex2f((c8)[1]);                             \
    float e2_=ex2f((c8)[2]), e3_=ex2f((c8)[3]);                             \
    float f0_=ex2f((c8)[4]), f1_=ex2f((c8)[5]);                             \
    float f2_=ex2f((c8)[6]), f3_=ex2f((c8)[7]);                             \
    lsum0 += e0_ + e1_ + f0_ + f1_;                                         \
    lsum1 += e2_ + e3_ + f2_ + f3_;                                         \
    CVT_BF16X2((P)[0], e0_, e1_);                                           \
    CVT_BF16X2((P)[1], e2_, e3_);                                           \
    CVT_BF16X2((P)[2], f0_, f1_);                                           \
    CVT_BF16X2((P)[3], f2_, f3_);                                           \
} while (0)

#define GEMM2_STEP(ks, P) do {                                              \
    const uint32_t va_ = vbase + (uint32_t)(ks) * 8448u;                    \
    _Pragma("unroll")                                                       \
    for (int jp2_ = 0; jp2_ < 16; jp2_++) {                                 \
        uint32_t bv4_[4];                                                   \
        ldsm4t(bv4_, va_ + jp2_ * 32);                                      \
        mma16816(o[2 * jp2_],     (P), bv4_);                               \
        mma16816(o[2 * jp2_ + 1], (P), bv4_ + 2);                           \
    }                                                                       \
} while (0)

__global__ __launch_bounds__(256, 1) void attn_kernel(
    const float* __restrict__ x,
    const float* __restrict__ gamma,
    const float* __restrict__ ln_w,
    const float* __restrict__ ln_b,
    float* __restrict__ out)
{
    extern __shared__ char dsm[];
    const uint32_t sb = smem_u32(dsm);

    const int b  = blockIdx.y;
    const int n0 = blockIdx.x * MQ;
    const int tid  = threadIdx.x;
    const int lane = tid & 31;
    const int warp = tid >> 5;
    const int wbase = warp * 16;
    const int qg = lane >> 2, qt = lane & 3;

    const __nv_bfloat16* qb = g_q + (size_t)b * NPIX * DDIM;
    const __nv_bfloat16* kb = g_k + (size_t)b * DDIM * NPIX;
    const __nv_bfloat16* vb = g_v + (size_t)b * NPIX * CDIM;

    // ---- prologue: Q + tile0 into buffer 0 ----
#pragma unroll
    for (int i = 0; i < 2; i++) {
        int idx = tid + i * 256;
        int row = idx >> 2, ch = idx & 3;
        CP_ASYNC16(sb + QS_OFF + row * 80 + ch * 16,
                   (const char*)(qb + (size_t)(n0 + row) * DDIM) + ch * 16);
    }
#pragma unroll
    for (int i = 0; i < 2; i++) {
        int idx = tid + i * 256;
        int d = idx >> 4, ch = idx & 15;
        CP_ASYNC16(sb + KS_OFF + d * 272 + ch * 16,
                   (const char*)(kb + (size_t)d * NPIX) + ch * 16);
    }
#pragma unroll
    for (int i = 0; i < 16; i++) {
        int idx = tid + i * 256;
        int row = idx >> 5, c2 = idx & 31;
        CP_ASYNC16(sb + VS_OFF + row * 528 + c2 * 16,
                   (const char*)(vb + (size_t)row * CDIM) + c2 * 16);
    }
    CP_COMMIT();

    uint32_t qa[2][4];
    float o[32][4];
#pragma unroll
    for (int nb = 0; nb < 32; nb++)
#pragma unroll
        for (int j = 0; j < 4; j++) o[nb][j] = 0.0f;
    float lsum0 = 0.0f, lsum1 = 0.0f;

    for (int kt = 0; kt < NTILES; kt++) {
        // issue next tile into the other buffer
        if (kt < NTILES - 1) {
            const int k0n = (kt + 1) * TK;
            const uint32_t bo = ((kt + 1) & 1) * BUFSTRIDE;
#pragma unroll
            for (int i = 0; i < 2; i++) {
                int idx = tid + i * 256;
                int d = idx >> 4, ch = idx & 15;
                CP_ASYNC16(sb + KS_OFF + bo + d * 272 + ch * 16,
                           (const char*)(kb + (size_t)d * NPIX + k0n) + ch * 16);
            }
#pragma unroll
            for (int i = 0; i < 16; i++) {
                int idx = tid + i * 256;
                int row = idx >> 5, c2 = idx & 31;
                CP_ASYNC16(sb + VS_OFF + bo + row * 528 + c2 * 16,
                           (const char*)(vb + (size_t)(k0n + row) * CDIM) + c2 * 16);
            }
            CP_COMMIT();
            CP_WAIT1();
        } else {
            CP_WAIT0();
        }
        __syncthreads();

        if (kt == 0) {
            int r  = wbase + (lane & 7) + ((lane >> 3) & 1) * 8;
            int cb = (lane >> 4) * 16;
            ldsm4(qa[0], sb + QS_OFF + r * 80 + cb);
            ldsm4(qa[1], sb + QS_OFF + r * 80 + 32 + cb);
        }

        const uint32_t bo = (kt & 1) * BUFSTRIDE;
        const uint32_t kaddr = sb + KS_OFF + bo + lane * 272;
        const uint32_t vbase = sb + VS_OFF + bo + (lane & 15) * 528 + (lane >> 4) * 16;

        // ---- software-pipelined: S(ks+1) issue overlaps GEMM2(ks) ----
        float cS[8];
        uint32_t Pc[4];
        S_STEP(0, cS);
        SOFTMAX_STEP(cS, Pc);
#pragma unroll
        for (int ks = 0; ks < 7; ks++) {
            float cN[8];
            S_STEP(ks + 1, cN);     // independent of Pc -> overlaps GEMM2 below
            GEMM2_STEP(ks, Pc);     // consumes Pc, covers S latency
            SOFTMAX_STEP(cN, Pc);   // produce next P
        }
        GEMM2_STEP(7, Pc);
        __syncthreads();
    }

    // ---- row sums -> scale (warp-local: warp saw all 4096 keys) ----
    lsum0 += __shfl_xor_sync(0xffffffffu, lsum0, 1);
    lsum0 += __shfl_xor_sync(0xffffffffu, lsum0, 2);
    lsum1 += __shfl_xor_sync(0xffffffffu, lsum1, 1);
    lsum1 += __shfl_xor_sync(0xffffffffu, lsum1, 2);
    const float gam = gamma[0];
    const float scl0 = gam / lsum0;
    const float scl1 = gam / lsum1;

    // ---- write scaled O to OutS (bf16, 516B row stride) ----
    {
        const uint32_t rbase = sb + OUTS_OFF + (uint32_t)(wbase + qg) * 516u;
#pragma unroll
        for (int nb = 0; nb < 32; nb++) {
            const uint32_t cbyte = (uint32_t)(nb * 8 + 2 * qt) * 2u;
            uint32_t p0, p1;
            CVT_BF16X2(p0, o[nb][0] * scl0, o[nb][1] * scl0);
            CVT_BF16X2(p1, o[nb][2] * scl1, o[nb][3] * scl1);
            STS32(rbase + cbyte, p0);
            STS32(rbase + 8u * 516u + cbyte, p1);
        }
    }
    __syncthreads();

    // ---- residual + LayerNorm: 256 threads = 256 channels, 2 x 64 pixels ----
    const int c = tid;
    const float lw = ln_w[c], lb = ln_b[c];
    float* wsum = reinterpret_cast<float*>(dsm + WS_OFF);
    float* wsq  = reinterpret_cast<float*>(dsm + WQ_OFF);
    float* mst  = reinterpret_cast<float*>(dsm + MST_OFF);
    float* lstd = reinterpret_cast<float*>(dsm + LSTD_OFF);
    const __nv_bfloat16* outs = reinterpret_cast<const __nv_bfloat16*>(dsm + OUTS_OFF);

    for (int hh = 0; hh < 2; hh++) {
        const int q0 = hh * 64;
        float Oc[64];
        const float* xrow = x + ((size_t)b * CDIM + c) * NPIX + n0 + q0;
#pragma unroll
        for (int j4 = 0; j4 < 16; j4++) {
            float4 xv = reinterpret_cast<const float4*>(xrow)[j4];
            float o0 = __bfloat162float(outs[(size_t)(q0 + 4 * j4 + 0) * 258 + c]);
            float o1 = __bfloat162float(outs[(size_t)(q0 + 4 * j4 + 1) * 258 + c]);
            float o2 = __bfloat162float(outs[(size_t)(q0 + 4 * j4 + 2) * 258 + c]);
            float o3 = __bfloat162float(outs[(size_t)(q0 + 4 * j4 + 3) * 258 + c]);
            Oc[4 * j4 + 0] = o0 + xv.x;
            Oc[4 * j4 + 1] = o1 + xv.y;
            Oc[4 * j4 + 2] = o2 + xv.z;
            Oc[4 * j4 + 3] = o3 + xv.w;
        }
#pragma unroll
        for (int q = 0; q < 64; q++) {
            float v = Oc[q];
            float s = v, s2 = v * v;
#pragma unroll
            for (int off = 16; off; off >>= 1) {
                s  += __shfl_xor_sync(0xffffffffu, s,  off);
                s2 += __shfl_xor_sync(0xffffffffu, s2, off);
            }
            if (lane == 0) { wsum[q * 8 + warp] = s; wsq[q * 8 + warp] = s2; }
        }
        __syncthreads();
        if (tid < 64) {
            float s = 0.0f, s2 = 0.0f;
#pragma unroll
            for (int w = 0; w < 8; w++) { s += wsum[tid * 8 + w]; s2 += wsq[tid * 8 + w]; }
            float mu  = s * (1.0f / CDIM);
            float var = s2 * (1.0f / CDIM) - mu * mu;
            mst[tid]  = mu;
            lstd[tid] = rsqrtf(var + LN_EPS);
        }
        __syncthreads();
        float* orow = out + ((size_t)b * CDIM + c) * NPIX + n0 + q0;
#pragma unroll
        for (int j4 = 0; j4 < 16; j4++) {
            float4 y;
            y.x = fmaf((Oc[4*j4 + 0] - mst[4*j4 + 0]) * lstd[4*j4 + 0], lw, lb);
            y.y = fmaf((Oc[4*j4 + 1] - mst[4*j4 + 1]) * lstd[4*j4 + 1], lw, lb);
            y.z = fmaf((Oc[4*j4 + 2] - mst[4*j4 + 2]) * lstd[4*j4 + 2], lw, lb);
            y.w = fmaf((Oc[4*j4 + 3] - mst[4*j4 + 3]) * lstd[4*j4 + 3], lw, lb);
            reinterpret_cast<float4*>(orow)[j4] = y;
        }
        __syncthreads();
    }
}

// ---------------------------------------------------------------------------
extern "C" void kernel_launch(void* const* d_in, const int* in_sizes, int n_in,
                              void* d_out, int out_size)
{
    const float* x     = (const float*)d_in[0];
    const float* wq    = (const float*)d_in[1];
    const float* bq    = (const float*)d_in[2];
    const float* wk    = (const float*)d_in[3];
    const float* bk    = (const float*)d_in[4];
    const float* wv    = (const float*)d_in[5];
    const float* bv    = (const float*)d_in[6];
    const float* gamma = (const float*)d_in[7];
    const float* ln_w  = (const float*)d_in[8];
    const float* ln_b  = (const float*)d_in[9];
    float* out = (float*)d_out;

    cudaFuncSetAttribute(attn_kernel, cudaFuncAttributeMaxDynamicSharedMemorySize, SMEM_DYN);

    qkv_kernel<<<dim3(NPIX / 256, 5, BATCH), 256>>>(x, wq, bq, wk, bk, wv, bv);
    attn_kernel<<<dim3(NPIX / MQ, BATCH), 256, SMEM_DYN>>>(x, gamma, ln_w, ln_b, out);
}

// round 16
// speedup vs baseline: 1.1825x; 1.0729x over previous
#include <cuda_runtime.h>
#include <cuda_bf16.h>
#include <cstdint>

// ---------------- problem constants ----------------
#define BATCH 4
#define CDIM  256
#define DDIM  32
#define NPIX  4096
#define LN_EPS 1e-5f
#define SCALE_LOG2E 0.2550348639f   // (1/sqrt(32)) * log2(e)

#define MQ 128                      // queries per CTA
#define TK 128                      // keys per tile
#define NTILES (NPIX / TK)          // 32

// ---------------- scratch (bf16, MMA-friendly layouts) ----------------
__device__ __nv_bfloat16 g_q[(size_t)BATCH * NPIX * DDIM];   // [b][n][d], pre-scaled
__device__ __nv_bfloat16 g_k[(size_t)BATCH * DDIM * NPIX];   // [b][d][n]
__device__ __nv_bfloat16 g_v[(size_t)BATCH * NPIX * CDIM];   // [b][n][c]

// ---------------- attn smem layout (bytes, dynamic) ----------------
// QS:  128 x 80B                       [0,      10240)
// KS0: 32 x 272B / VS0: 128 x 528B     [10240,  86528)
// KS1 / VS1 (double buffer)            [86528, 162816)
// OutS overlay (128 x 516B)            [10240,  76288)
#define QS_OFF    0
#define KS_OFF    10240
#define VS_OFF    18944
#define BUFSTRIDE 76288
#define OUTS_OFF  10240
#define WS_OFF    162816
#define WQ_OFF    166912
#define MST_OFF   171008
#define LSTD_OFF  171520
#define SMEM_DYN  172032

// ---------------- PTX helpers (sm_100 base-target safe) ----------------
__device__ __forceinline__ uint32_t smem_u32(const void* p) {
    uint32_t a;
    asm("{ .reg .u64 t; cvta.to.shared.u64 t, %1; cvt.u32.u64 %0, t; }" : "=r"(a) : "l"(p));
    return a;
}
__device__ __forceinline__ float ex2f(float v) {
    float y; asm("ex2.approx.ftz.f32 %0, %1;" : "=f"(y) : "f"(v)); return y;
}
__device__ __forceinline__ void ldsm4(uint32_t* r, uint32_t addr) {
    asm volatile("ldmatrix.sync.aligned.m8n8.x4.shared.b16 {%0,%1,%2,%3}, [%4];"
                 : "=r"(r[0]), "=r"(r[1]), "=r"(r[2]), "=r"(r[3]) : "r"(addr));
}
__device__ __forceinline__ void ldsm4t(uint32_t* r, uint32_t addr) {
    asm volatile("ldmatrix.sync.aligned.m8n8.x4.trans.shared.b16 {%0,%1,%2,%3}, [%4];"
                 : "=r"(r[0]), "=r"(r[1]), "=r"(r[2]), "=r"(r[3]) : "r"(addr));
}
__device__ __forceinline__ void mma16816(float* c, const uint32_t* a, const uint32_t* b) {
    asm volatile("mma.sync.aligned.m16n8k16.row.col.f32.bf16.bf16.f32 "
                 "{%0,%1,%2,%3}, {%4,%5,%6,%7}, {%8,%9}, {%0,%1,%2,%3};"
                 : "+f"(c[0]), "+f"(c[1]), "+f"(c[2]), "+f"(c[3])
                 : "r"(a[0]), "r"(a[1]), "r"(a[2]), "r"(a[3]), "r"(b[0]), "r"(b[1]));
}
#define CP_ASYNC16(dst, src) \
    asm volatile("cp.async.cg.shared.global [%0], [%1], 16;" :: "r"(dst), "l"(src))
#define CP_COMMIT() asm volatile("cp.async.commit_group;" ::: "memory")
#define CP_WAIT0()  asm volatile("cp.async.wait_group 0;" ::: "memory")
#define CP_WAIT1()  asm volatile("cp.async.wait_group 1;" ::: "memory")
#define STS32(addr, a) \
    asm volatile("st.shared.b32 [%0], %1;" :: "r"(addr), "r"(a) : "memory")
#define STS16(addr, h) \
    asm volatile("st.shared.b16 [%0], %1;" :: "r"(addr), "h"(h) : "memory")
#define LDS32(res, addr) \
    asm volatile("ld.shared.b32 %0, [%1];" : "=r"(res) : "r"(addr))
#define LDS16(res, addr) \
    asm volatile("ld.shared.b16 %0, [%1];" : "=h"(res) : "r"(addr))
// pack {hi:lo} bf16x2
#define CVT_BF16X2(res, lo, hi) \
    asm("cvt.rn.bf16x2.f32 %0, %1, %2;" : "=r"(res) : "f"(hi), "f"(lo))

__device__ __forceinline__ uint16_t bf16_bits(float v) {
    uint32_t p; CVT_BF16X2(p, v, 0.0f); return (uint16_t)(p & 0xFFFFu);
}

// ---------------------------------------------------------------------------
// Kernel 1: QKV projection via bf16 mma.sync.
// Round-15: 128-wide tiling (r10) + register-prefetch of next k-iteration's
// W/X fp32 loads so LDG latency hides under the current iteration's mma.
// ---------------------------------------------------------------------------
#define WT_OFF 0        // 64 rows x 80B  = 5120
#define XT_OFF 5120     // 32 rows x 272B = 8704

__global__ __launch_bounds__(256) void qkv_kernel(
    const float* __restrict__ x,
    const float* __restrict__ wq, const float* __restrict__ bq,
    const float* __restrict__ wk, const float* __restrict__ bk,
    const float* __restrict__ wv, const float* __restrict__ bv)
{
    __shared__ __align__(16) char qsm[16896];
    const uint32_t sb = smem_u32(qsm);

    const int b  = blockIdx.z;
    const int n0 = blockIdx.x * 128;
    const int r0 = blockIdx.y * 64;
    const int tid  = threadIdx.x;
    const int lane = tid & 31;
    const int warp = tid >> 5;
    const int rgrp  = (warp & 3) * 16;
    const int nhalf = (warp >> 2) * 64;
    const int qg = lane >> 2, qt = lane & 3;
    const float* xb = x + (size_t)b * CDIM * NPIX;

    // per-thread gmem source descriptors (fixed across iterations)
    const int wr = tid >> 4, wcp = (tid & 15) * 2;          // W: 4 chunks of (r, cp)
    const int xk = tid >> 6, xnp = (tid & 63) * 2;          // X: 8 chunks of (k, np)

    float2 wreg[4];
    float2 xreg[8];

    // ---- prefetch iteration 0 ----
#pragma unroll
    for (int l = 0; l < 4; l++) {
        int r = wr + l * 16;            // (tid + l*256) >> 4
        int rg = r0 + r, c = wcp;
        const float* ws;
        if (rg < DDIM)            ws = wq + rg * CDIM + c;
        else if (rg < 2 * DDIM)   ws = wk + (rg - DDIM) * CDIM + c;
        else                      ws = wv + (rg - 2 * DDIM) * CDIM + c;
        wreg[l] = *reinterpret_cast<const float2*>(ws);
    }
#pragma unroll
    for (int l = 0; l < 8; l++) {
        int k = xk + l * 4;             // (tid + l*256) >> 6
        xreg[l] = *reinterpret_cast<const float2*>(xb + (size_t)k * NPIX + n0 + xnp);
    }

    float acc[8][4];
#pragma unroll
    for (int i = 0; i < 8; i++)
#pragma unroll
        for (int j = 0; j < 4; j++) acc[i][j] = 0.0f;

    for (int kk = 0; kk < CDIM; kk += 32) {
        // ---- convert + store current iteration's tiles ----
#pragma unroll
        for (int l = 0; l < 4; l++) {
            int r = wr + l * 16;
            uint32_t pw; CVT_BF16X2(pw, wreg[l].x, wreg[l].y);
            STS32(sb + WT_OFF + r * 80 + wcp * 2, pw);
        }
#pragma unroll
        for (int l = 0; l < 8; l++) {
            int k = xk + l * 4;
            uint32_t px; CVT_BF16X2(px, xreg[l].x, xreg[l].y);
            STS32(sb + XT_OFF + k * 272 + xnp * 2, px);
        }
        __syncthreads();

        // ---- prefetch next iteration (LDGs overlap mma below) ----
        if (kk < CDIM - 32) {
            const int kn = kk + 32;
#pragma unroll
            for (int l = 0; l < 4; l++) {
                int r = wr + l * 16;
                int rg = r0 + r, c = kn + wcp;
                const float* ws;
                if (rg < DDIM)            ws = wq + rg * CDIM + c;
                else if (rg < 2 * DDIM)   ws = wk + (rg - DDIM) * CDIM + c;
                else                      ws = wv + (rg - 2 * DDIM) * CDIM + c;
                wreg[l] = *reinterpret_cast<const float2*>(ws);
            }
#pragma unroll
            for (int l = 0; l < 8; l++) {
                int k = xk + l * 4;
                xreg[l] = *reinterpret_cast<const float2*>(
                    xb + (size_t)(kn + k) * NPIX + n0 + xnp);
            }
        }

        // ---- MMA over this k-slab ----
        uint32_t wa[2][4];
        {
            int r = rgrp + (lane & 7) + ((lane >> 3) & 1) * 8;
            int cb = (lane >> 4) * 16;
            ldsm4(wa[0], sb + WT_OFF + r * 80 + cb);
            ldsm4(wa[1], sb + WT_OFF + r * 80 + 32 + cb);
        }
        const uint32_t xaddr = sb + XT_OFF + lane * 272 + nhalf * 2;
#pragma unroll
        for (int nb = 0; nb < 8; nb++) {
            uint32_t bx[4];
            ldsm4t(bx, xaddr + nb * 16);
            mma16816(acc[nb], wa[0], bx);
            mma16816(acc[nb], wa[1], bx + 2);
        }
        __syncthreads();
    }

    // ---- bias + stage into T[n][r] (bf16, 132B row stride) ----
#pragma unroll
    for (int half = 0; half < 2; half++) {
        int rl = rgrp + qg + half * 8;
        int rg = r0 + rl;
        float bias;
        if (rg < DDIM)          bias = bq[rg];
        else if (rg < 2 * DDIM) bias = bk[rg - DDIM];
        else                    bias = bv[rg - 2 * DDIM];
        float mult = (rg < DDIM) ? SCALE_LOG2E : 1.0f;
#pragma unroll
        for (int nb = 0; nb < 8; nb++) {
            int nl = nhalf + nb * 8 + qt * 2;
            float v0 = (acc[nb][half * 2 + 0] + bias) * mult;
            float v1 = (acc[nb][half * 2 + 1] + bias) * mult;
            STS16(sb + nl * 132 + rl * 2, bf16_bits(v0));
            STS16(sb + (nl + 1) * 132 + rl * 2, bf16_bits(v1));
        }
    }
    __syncthreads();

    if (r0 == 0) {
        // q rows 0..31 -> g_q[b][n][d]
#pragma unroll
        for (int l = 0; l < 8; l++) {
            int idx = tid + l * 256;
            int n = idx >> 4, rp = (idx & 15) * 2;
            uint32_t w; LDS32(w, sb + n * 132 + rp * 2);
            *reinterpret_cast<uint32_t*>(&g_q[((size_t)b * NPIX + n0 + n) * DDIM + rp]) = w;
        }
        // k rows 32..63 -> g_k[b][d][n]
#pragma unroll
        for (int l = 0; l < 8; l++) {
            int idx = tid + l * 256;
            int r = 32 + (idx >> 6), np = (idx & 63) * 2;
            uint16_t h0, h1;
            LDS16(h0, sb + np * 132 + r * 2);
            LDS16(h1, sb + (np + 1) * 132 + r * 2);
            uint32_t w = (uint32_t)h0 | ((uint32_t)h1 << 16);
            *reinterpret_cast<uint32_t*>(&g_k[((size_t)b * DDIM + (r - 32)) * NPIX + n0 + np]) = w;
        }
    } else {
        // v channels [r0-64, r0) -> g_v[b][n][c]
#pragma unroll
        for (int l = 0; l < 16; l++) {
            int idx = tid + l * 256;
            int n = idx >> 5, cp = (idx & 31) * 2;
            uint32_t w; LDS32(w, sb + n * 132 + cp * 2);
            *reinterpret_cast<uint32_t*>(&g_v[((size_t)b * NPIX + n0 + n) * CDIM + (r0 - 64) + cp]) = w;
        }
    }
}

// ---------------------------------------------------------------------------
// Kernel 2: mma.sync bf16 flash attention + gamma residual + LayerNorm.
// Round-10 champion, verbatim. 256 threads / 8 warps: warp = 16 queries x
// ALL 256 channels, 255-reg budget, double-buffered K/V, pipelined tile loop.
// ---------------------------------------------------------------------------

#define S_STEP(s, c8) do {                                                  \
    uint32_t bk4a_[4], bk4b_[4];                                            \
    (c8)[0]=(c8)[1]=(c8)[2]=(c8)[3]=0.0f;                                   \
    (c8)[4]=(c8)[5]=(c8)[6]=(c8)[7]=0.0f;                                   \
    ldsm4t(bk4a_, kaddr + (uint32_t)(2*(s)) * 16u);                         \
    ldsm4t(bk4b_, kaddr + (uint32_t)(2*(s)+1) * 16u);                       \
    mma16816((c8),     qa[0], bk4a_);                                       \
    mma16816((c8) + 4, qa[0], bk4b_);                                       \
    mma16816((c8),     qa[1], bk4a_ + 2);                                   \
    mma16816((c8) + 4, qa[1], bk4b_ + 2);                                   \
} while (0)

#define SOFTMAX_STEP(c8, P) do {                                            \
    float e0_=ex2f((c8)[0]), e1_=ex2f((c8)[1]);                             \
    float e2_=ex2f((c8)[2]), e3_=ex2f((c8)[3]);                             \
    float f0_=ex2f((c8)[4]), f1_=ex2f((c8)[5]);                             \
    float f2_=ex2f((c8)[6]), f3_=ex2f((c8)[7]);                             \
    lsum0 += e0_ + e1_ + f0_ + f1_;                                         \
    lsum1 += e2_ + e3_ + f2_ + f3_;                                         \
    CVT_BF16X2((P)[0], e0_, e1_);                                           \
    CVT_BF16X2((P)[1], e2_, e3_);                                           \
    CVT_BF16X2((P)[2], f0_, f1_);                                           \
    CVT_BF16X2((P)[3], f2_, f3_);                                           \
} while (0)

#define GEMM2_STEP(ks, P) do {                                              \
    const uint32_t va_ = vbase + (uint32_t)(ks) * 8448u;                    \
    _Pragma("unroll")                                                       \
    for (int jp2_ = 0; jp2_ < 16; jp2_++) {                                 \
        uint32_t bv4_[4];                                                   \
        ldsm4t(bv4_, va_ + jp2_ * 32);                                      \
        mma16816(o[2 * jp2_],     (P), bv4_);                               \
        mma16816(o[2 * jp2_ + 1], (P), bv4_ + 2);                           \
    }                                                                       \
} while (0)

__global__ __launch_bounds__(256, 1) void attn_kernel(
    const float* __restrict__ x,
    const float* __restrict__ gamma,
    const float* __restrict__ ln_w,
    const float* __restrict__ ln_b,
    float* __restrict__ out)
{
    extern __shared__ char dsm[];
    const uint32_t sb = smem_u32(dsm);

    const int b  = blockIdx.y;
    const int n0 = blockIdx.x * MQ;
    const int tid  = threadIdx.x;
    const int lane = tid & 31;
    const int warp = tid >> 5;
    const int wbase = warp * 16;
    const int qg = lane >> 2, qt = lane & 3;

    const __nv_bfloat16* qb = g_q + (size_t)b * NPIX * DDIM;
    const __nv_bfloat16* kb = g_k + (size_t)b * DDIM * NPIX;
    const __nv_bfloat16* vb = g_v + (size_t)b * NPIX * CDIM;

    // ---- prologue: Q + tile0 into buffer 0 ----
#pragma unroll
    for (int i = 0; i < 2; i++) {
        int idx = tid + i * 256;
        int row = idx >> 2, ch = idx & 3;
        CP_ASYNC16(sb + QS_OFF + row * 80 + ch * 16,
                   (const char*)(qb + (size_t)(n0 + row) * DDIM) + ch * 16);
    }
#pragma unroll
    for (int i = 0; i < 2; i++) {
        int idx = tid + i * 256;
        int d = idx >> 4, ch = idx & 15;
        CP_ASYNC16(sb + KS_OFF + d * 272 + ch * 16,
                   (const char*)(kb + (size_t)d * NPIX) + ch * 16);
    }
#pragma unroll
    for (int i = 0; i < 16; i++) {
        int idx = tid + i * 256;
        int row = idx >> 5, c2 = idx & 31;
        CP_ASYNC16(sb + VS_OFF + row * 528 + c2 * 16,
                   (const char*)(vb + (size_t)row * CDIM) + c2 * 16);
    }
    CP_COMMIT();

    uint32_t qa[2][4];
    float o[32][4];
#pragma unroll
    for (int nb = 0; nb < 32; nb++)
#pragma unroll
        for (int j = 0; j < 4; j++) o[nb][j] = 0.0f;
    float lsum0 = 0.0f, lsum1 = 0.0f;

    for (int kt = 0; kt < NTILES; kt++) {
        // issue next tile into the other buffer
        if (kt < NTILES - 1) {
            const int k0n = (kt + 1) * TK;
            const uint32_t bo = ((kt + 1) & 1) * BUFSTRIDE;
#pragma unroll
            for (int i = 0; i < 2; i++) {
                int idx = tid + i * 256;
                int d = idx >> 4, ch = idx & 15;
                CP_ASYNC16(sb + KS_OFF + bo + d * 272 + ch * 16,
                           (const char*)(kb + (size_t)d * NPIX + k0n) + ch * 16);
            }
#pragma unroll
            for (int i = 0; i < 16; i++) {
                int idx = tid + i * 256;
                int row = idx >> 5, c2 = idx & 31;
                CP_ASYNC16(sb + VS_OFF + bo + row * 528 + c2 * 16,
                           (const char*)(vb + (size_t)(k0n + row) * CDIM) + c2 * 16);
            }
            CP_COMMIT();
            CP_WAIT1();
        } else {
            CP_WAIT0();
        }
        __syncthreads();

        if (kt == 0) {
            int r  = wbase + (lane & 7) + ((lane >> 3) & 1) * 8;
            int cb = (lane >> 4) * 16;
            ldsm4(qa[0], sb + QS_OFF + r * 80 + cb);
            ldsm4(qa[1], sb + QS_OFF + r * 80 + 32 + cb);
        }

        const uint32_t bo = (kt & 1) * BUFSTRIDE;
        const uint32_t kaddr = sb + KS_OFF + bo + lane * 272;
        const uint32_t vbase = sb + VS_OFF + bo + (lane & 15) * 528 + (lane >> 4) * 16;

        // ---- software-pipelined: S(ks+1) issue overlaps GEMM2(ks) ----
        float cS[8];
        uint32_t Pc[4];
        S_STEP(0, cS);
        SOFTMAX_STEP(cS, Pc);
#pragma unroll
        for (int ks = 0; ks < 7; ks++) {
            float cN[8];
            S_STEP(ks + 1, cN);     // independent of Pc -> overlaps GEMM2 below
            GEMM2_STEP(ks, Pc);     // consumes Pc, covers S latency
            SOFTMAX_STEP(cN, Pc);   // produce next P
        }
        GEMM2_STEP(7, Pc);
        __syncthreads();
    }

    // ---- row sums -> scale (warp-local: warp saw all 4096 keys) ----
    lsum0 += __shfl_xor_sync(0xffffffffu, lsum0, 1);
    lsum0 += __shfl_xor_sync(0xffffffffu, lsum0, 2);
    lsum1 += __shfl_xor_sync(0xffffffffu, lsum1, 1);
    lsum1 += __shfl_xor_sync(0xffffffffu, lsum1, 2);
    const float gam = gamma[0];
    const float scl0 = gam / lsum0;
    const float scl1 = gam / lsum1;

    // ---- write scaled O to OutS (bf16, 516B row stride) ----
    {
        const uint32_t rbase = sb + OUTS_OFF + (uint32_t)(wbase + qg) * 516u;
#pragma unroll
        for (int nb = 0; nb < 32; nb++) {
            const uint32_t cbyte = (uint32_t)(nb * 8 + 2 * qt) * 2u;
            uint32_t p0, p1;
            CVT_BF16X2(p0, o[nb][0] * scl0, o[nb][1] * scl0);
            CVT_BF16X2(p1, o[nb][2] * scl1, o[nb][3] * scl1);
            STS32(rbase + cbyte, p0);
            STS32(rbase + 8u * 516u + cbyte, p1);
        }
    }
    __syncthreads();

    // ---- residual + LayerNorm: 256 threads = 256 channels, 2 x 64 pixels ----
    const int c = tid;
    const float lw = ln_w[c], lb = ln_b[c];
    float* wsum = reinterpret_cast<float*>(dsm + WS_OFF);
    float* wsq  = reinterpret_cast<float*>(dsm + WQ_OFF);
    float* mst  = reinterpret_cast<float*>(dsm + MST_OFF);
    float* lstd = reinterpret_cast<float*>(dsm + LSTD_OFF);
    const __nv_bfloat16* outs = reinterpret_cast<const __nv_bfloat16*>(dsm + OUTS_OFF);

    for (int hh = 0; hh < 2; hh++) {
        const int q0 = hh * 64;
        float Oc[64];
        const float* xrow = x + ((size_t)b * CDIM + c) * NPIX + n0 + q0;
#pragma unroll
        for (int j4 = 0; j4 < 16; j4++) {
            float4 xv = reinterpret_cast<const float4*>(xrow)[j4];
            float o0 = __bfloat162float(outs[(size_t)(q0 + 4 * j4 + 0) * 258 + c]);
            float o1 = __bfloat162float(outs[(size_t)(q0 + 4 * j4 + 1) * 258 + c]);
            float o2 = __bfloat162float(outs[(size_t)(q0 + 4 * j4 + 2) * 258 + c]);
            float o3 = __bfloat162float(outs[(size_t)(q0 + 4 * j4 + 3) * 258 + c]);
            Oc[4 * j4 + 0] = o0 + xv.x;
            Oc[4 * j4 + 1] = o1 + xv.y;
            Oc[4 * j4 + 2] = o2 + xv.z;
            Oc[4 * j4 + 3] = o3 + xv.w;
        }
#pragma unroll
        for (int q = 0; q < 64; q++) {
            float v = Oc[q];
            float s = v, s2 = v * v;
#pragma unroll
            for (int off = 16; off; off >>= 1) {
                s  += __shfl_xor_sync(0xffffffffu, s,  off);
                s2 += __shfl_xor_sync(0xffffffffu, s2, off);
            }
            if (lane == 0) { wsum[q * 8 + warp] = s; wsq[q * 8 + warp] = s2; }
        }
        __syncthreads();
        if (tid < 64) {
            float s = 0.0f, s2 = 0.0f;
#pragma unroll
            for (int w = 0; w < 8; w++) { s += wsum[tid * 8 + w]; s2 += wsq[tid * 8 + w]; }
            float mu  = s * (1.0f / CDIM);
            float var = s2 * (1.0f / CDIM) - mu * mu;
            mst[tid]  = mu;
            lstd[tid] = rsqrtf(var + LN_EPS);
        }
        __syncthreads();
        float* orow = out + ((size_t)b * CDIM + c) * NPIX + n0 + q0;
#pragma unroll
        for (int j4 = 0; j4 < 16; j4++) {
            float4 y;
            y.x = fmaf((Oc[4*j4 + 0] - mst[4*j4 + 0]) * lstd[4*j4 + 0], lw, lb);
            y.y = fmaf((Oc[4*j4 + 1] - mst[4*j4 + 1]) * lstd[4*j4 + 1], lw, lb);
            y.z = fmaf((Oc[4*j4 + 2] - mst[4*j4 + 2]) * lstd[4*j4 + 2], lw, lb);
            y.w = fmaf((Oc[4*j4 + 3] - mst[4*j4 + 3]) * lstd[4*j4 + 3], lw, lb);
            reinterpret_cast<float4*>(orow)[j4] = y;
        }
        __syncthreads();
    }
}

// ---------------------------------------------------------------------------
extern "C" void kernel_launch(void* const* d_in, const int* in_sizes, int n_in,
                              void* d_out, int out_size)
{
    const float* x     = (const float*)d_in[0];
    const float* wq    = (const float*)d_in[1];
    const float* bq    = (const float*)d_in[2];
    const float* wk    = (const float*)d_in[3];
    const float* bk    = (const float*)d_in[4];
    const float* wv    = (const float*)d_in[5];
    const float* bv    = (const float*)d_in[6];
    const float* gamma = (const float*)d_in[7];
    const float* ln_w  = (const float*)d_in[8];
    const float* ln_b  = (const float*)d_in[9];
    float* out = (float*)d_out;

    cudaFuncSetAttribute(attn_kernel, cudaFuncAttributeMaxDynamicSharedMemorySize, SMEM_DYN);

    qkv_kernel<<<dim3(NPIX / 128, 5, BATCH), 256>>>(x, wq, bq, wk, bk, wv, bv);
    attn_kernel<<<dim3(NPIX / MQ, BATCH), 256, SMEM_DYN>>>(x, gamma, ln_w, ln_b, out);
}